// round 3
// baseline (speedup 1.0000x reference)
#include <cuda_runtime.h>

// NSLayer: out = x + (w0*A + w1*A^2 + ... + w6*A^7 + w7*I) @ x,  A = I - x x^T
// x: (2048, 128, 8, 8) fp32  ->  262144 independent 8x8 matrices.
//
// One thread per matrix, fully register-resident:
//   - A is symmetric -> keep upper triangle only (36 regs)
//   - vector Horner:  z = w6*x; z = w_t*x + A z (t=5..0); out = (1+w7)*x + A z
//   - process z in 2-column slabs (independent columns) to bound live registers.

#define NMAT (2048 * 128)

// upper-triangle index for i <= j
__device__ __forceinline__ float Aget(const float* At, int i, int j) {
    int a = i < j ? i : j;
    int b = i < j ? j : i;
    return At[a * 8 - (a * (a + 1)) / 2 + b];
}

__global__ __launch_bounds__(256, 1) void nslayer_kernel(
    const float* __restrict__ x_g,
    const float* __restrict__ w_g,
    float* __restrict__ out_g)
{
    const int m = blockIdx.x * blockDim.x + threadIdx.x;
    if (m >= NMAT) return;

    const float4* xm4 = reinterpret_cast<const float4*>(x_g + (size_t)m * 64);

    float x[64];
#pragma unroll
    for (int i = 0; i < 16; ++i) {
        float4 v = __ldg(xm4 + i);
        x[i * 4 + 0] = v.x;
        x[i * 4 + 1] = v.y;
        x[i * 4 + 2] = v.z;
        x[i * 4 + 3] = v.w;
    }

    float w[8];
#pragma unroll
    for (int i = 0; i < 8; ++i) w[i] = __ldg(w_g + i);
    const float w7p1 = 1.0f + w[7];

    // ---- A = I - x x^T (symmetric, upper triangle) ----
    float At[36];
#pragma unroll
    for (int i = 0; i < 8; ++i) {
#pragma unroll
        for (int j = 0; j < 8; ++j) {
            if (j >= i) {
                float s = x[i * 8 + 0] * x[j * 8 + 0];
#pragma unroll
                for (int k = 1; k < 8; ++k)
                    s = fmaf(x[i * 8 + k], x[j * 8 + k], s);
                At[i * 8 - (i * (i + 1)) / 2 + j] = (i == j ? 1.0f : 0.0f) - s;
            }
        }
    }

    // ---- Horner in 2-column slabs ----
    float* outm = out_g + (size_t)m * 64;

#pragma unroll
    for (int s = 0; s < 4; ++s) {
        const int c0 = 2 * s;
        const int c1 = 2 * s + 1;

        float z0[8], z1[8];
#pragma unroll
        for (int i = 0; i < 8; ++i) {
            z0[i] = w[6] * x[i * 8 + c0];
            z1[i] = w[6] * x[i * 8 + c1];
        }

#pragma unroll
        for (int t = 5; t >= 0; --t) {
            float n0[8], n1[8];
#pragma unroll
            for (int i = 0; i < 8; ++i) {
                float a0 = w[t] * x[i * 8 + c0];
                float a1 = w[t] * x[i * 8 + c1];
#pragma unroll
                for (int k = 0; k < 8; ++k) {
                    float a = Aget(At, i, k);
                    a0 = fmaf(a, z0[k], a0);
                    a1 = fmaf(a, z1[k], a1);
                }
                n0[i] = a0;
                n1[i] = a1;
            }
#pragma unroll
            for (int i = 0; i < 8; ++i) { z0[i] = n0[i]; z1[i] = n1[i]; }
        }

        // out = (1 + w7) * x + A z
#pragma unroll
        for (int i = 0; i < 8; ++i) {
            float a0 = w7p1 * x[i * 8 + c0];
            float a1 = w7p1 * x[i * 8 + c1];
#pragma unroll
            for (int k = 0; k < 8; ++k) {
                float a = Aget(At, i, k);
                a0 = fmaf(a, z0[k], a0);
                a1 = fmaf(a, z1[k], a1);
            }
            float2 o;
            o.x = a0;
            o.y = a1;
            *reinterpret_cast<float2*>(outm + i * 8 + c0) = o;
        }
    }
}

extern "C" void kernel_launch(void* const* d_in, const int* in_sizes, int n_in,
                              void* d_out, int out_size) {
    const float* x_g = (const float*)d_in[0];   // (2048,128,8,8) fp32
    const float* w_g = (const float*)d_in[1];   // 14 fp32 (w[0..7] used)
    float* out_g = (float*)d_out;

    const int threads = 256;
    const int blocks = (NMAT + threads - 1) / threads;
    nslayer_kernel<<<blocks, threads>>>(x_g, w_g, out_g);
}

// round 4
// speedup vs baseline: 1.0632x; 1.0632x over previous
#include <cuda_runtime.h>

// NSLayer: out = x + (w0*A + ... + w6*A^7 + w7*I) @ x,  A = I - x x^T
// Gram-space identity: A^k x = x B^k with B = I - x^T x (symmetric 8x8).
//   out = x * P,  P = (1+w7) I + sum_{k=1..7} w_{k-1} B^k   (P symmetric)
// Horner on triangles only:
//   M = w5 I + w6 B;  M = w_t I + B*M (t=4..0);  P = (1+w7) I + B*M
// x is reloaded (asm volatile, no CSE) for the final x*P so registers stay
// under 128 -> 2 CTAs/SM.

#define NMAT (2048 * 128)

__device__ __forceinline__ int tri(int i, int j) {          // i <= j
    return i * 8 - (i * (i + 1)) / 2 + j;
}
__device__ __forceinline__ float sg(const float* T, int i, int j) {
    return (i <= j) ? T[tri(i, j)] : T[tri(j, i)];
}

// dst = B * src + wt * I   (all symmetric, triangle storage)
__device__ __forceinline__ void step(float* __restrict__ dst,
                                     const float* __restrict__ B,
                                     const float* __restrict__ src,
                                     float wt) {
#pragma unroll
    for (int i = 0; i < 8; ++i) {
#pragma unroll
        for (int j = i; j < 8; ++j) {
            float s = sg(B, i, 0) * sg(src, 0, j);
#pragma unroll
            for (int k = 1; k < 8; ++k)
                s = fmaf(sg(B, i, k), sg(src, k, j), s);
            dst[tri(i, j)] = (i == j) ? (s + wt) : s;
        }
    }
}

// volatile global load: prevents CSE with the first x load so x's registers
// are dead during the Horner chain.
__device__ __forceinline__ float4 ldg4v(const float4* p) {
    float4 v;
    asm volatile("ld.global.nc.v4.f32 {%0,%1,%2,%3}, [%4];"
                 : "=f"(v.x), "=f"(v.y), "=f"(v.z), "=f"(v.w)
                 : "l"(p));
    return v;
}

__global__ __launch_bounds__(256, 2) void nslayer_kernel(
    const float* __restrict__ x_g,
    const float* __restrict__ w_g,
    float* __restrict__ out_g)
{
    const int m = blockIdx.x * blockDim.x + threadIdx.x;
    if (m >= NMAT) return;

    const float4* xm4 = reinterpret_cast<const float4*>(x_g + (size_t)m * 64);

    float w[8];
#pragma unroll
    for (int i = 0; i < 8; ++i) w[i] = __ldg(w_g + i);

    // ---- load x, build B = I - x^T x (upper triangle) ----
    float B[36];
    {
        float x[64];
#pragma unroll
        for (int i = 0; i < 16; ++i) {
            float4 v = __ldg(xm4 + i);
            x[i * 4 + 0] = v.x;
            x[i * 4 + 1] = v.y;
            x[i * 4 + 2] = v.z;
            x[i * 4 + 3] = v.w;
        }
#pragma unroll
        for (int i = 0; i < 8; ++i) {
#pragma unroll
            for (int j = i; j < 8; ++j) {
                float s = x[0 * 8 + i] * x[0 * 8 + j];
#pragma unroll
                for (int k = 1; k < 8; ++k)
                    s = fmaf(x[k * 8 + i], x[k * 8 + j], s);
                B[tri(i, j)] = (i == j ? 1.0f : 0.0f) - s;
            }
        }
    }

    // ---- Horner chain on symmetric triangles ----
    float M0[36], M1[36];
#pragma unroll
    for (int i = 0; i < 8; ++i) {
#pragma unroll
        for (int j = i; j < 8; ++j)
            M0[tri(i, j)] = w[6] * B[tri(i, j)] + (i == j ? w[5] : 0.0f);
    }
    step(M1, B, M0, w[4]);
    step(M0, B, M1, w[3]);
    step(M1, B, M0, w[2]);
    step(M0, B, M1, w[1]);
    step(M1, B, M0, w[0]);
    step(M0, B, M1, 1.0f + w[7]);   // M0 = P = (1+w7) I + B*H

    // ---- out = x * P, streaming x row-by-row (reloaded, L2-resident) ----
    float4* om4 = reinterpret_cast<float4*>(out_g + (size_t)m * 64);
#pragma unroll
    for (int i = 0; i < 8; ++i) {
        float4 a = ldg4v(xm4 + 2 * i);
        float4 b = ldg4v(xm4 + 2 * i + 1);
        float xr[8] = {a.x, a.y, a.z, a.w, b.x, b.y, b.z, b.w};

        float acc[8];
#pragma unroll
        for (int j = 0; j < 8; ++j) {
            float s = xr[0] * sg(M0, 0, j);
#pragma unroll
            for (int k = 1; k < 8; ++k)
                s = fmaf(xr[k], sg(M0, k, j), s);
            acc[j] = s;
        }
        float4 o0 = {acc[0], acc[1], acc[2], acc[3]};
        float4 o1 = {acc[4], acc[5], acc[6], acc[7]};
        om4[2 * i + 0] = o0;
        om4[2 * i + 1] = o1;
    }
}

extern "C" void kernel_launch(void* const* d_in, const int* in_sizes, int n_in,
                              void* d_out, int out_size) {
    const float* x_g = (const float*)d_in[0];   // (2048,128,8,8) fp32
    const float* w_g = (const float*)d_in[1];   // 14 fp32 (w[0..7] used)
    float* out_g = (float*)d_out;

    const int threads = 256;
    const int blocks = (NMAT + threads - 1) / threads;
    nslayer_kernel<<<blocks, threads>>>(x_g, w_g, out_g);
}

// round 5
// speedup vs baseline: 1.9797x; 1.8621x over previous
#include <cuda_runtime.h>

// NSLayer: out = x + (w0*A + ... + w6*A^7 + w7*I) @ x,  A = I - x x^T
// Gram-space identity: A^k x = x B^k with B = I - x^T x (symmetric 8x8).
//   out = x * P,  P = (1+w7) I + sum_{k=1..7} w_{k-1} B^k   (P symmetric)
// Horner on symmetric triangles only (products of commuting symmetric
// polynomials in B are symmetric):
//   M = w6 B + w5 I;  M = w_t I + B*M (t=4..0);  P = (1+w7) I + B*M
//
// R4 lesson: this chain needs ~135 live regs; a 128-reg cap caused spills
// (DRAM 36%, 2x traffic). Use 128-thread blocks, 3 CTAs/SM -> ~170-reg cap:
// no spills, 12 warps/SM.

#define NMAT (2048 * 128)

__device__ __forceinline__ int tri(int i, int j) {          // i <= j
    return i * 8 - (i * (i + 1)) / 2 + j;
}
__device__ __forceinline__ float sg(const float* T, int i, int j) {
    return (i <= j) ? T[tri(i, j)] : T[tri(j, i)];
}

// dst = B * src + wt * I   (all symmetric, triangle storage)
__device__ __forceinline__ void step(float* __restrict__ dst,
                                     const float* __restrict__ B,
                                     const float* __restrict__ src,
                                     float wt) {
#pragma unroll
    for (int i = 0; i < 8; ++i) {
#pragma unroll
        for (int j = i; j < 8; ++j) {
            float s = sg(B, i, 0) * sg(src, 0, j);
#pragma unroll
            for (int k = 1; k < 8; ++k)
                s = fmaf(sg(B, i, k), sg(src, k, j), s);
            dst[tri(i, j)] = (i == j) ? (s + wt) : s;
        }
    }
}

// volatile global load: prevents CSE with the first x load so x's registers
// are dead during the Horner chain.
__device__ __forceinline__ float4 ldg4v(const float4* p) {
    float4 v;
    asm volatile("ld.global.nc.v4.f32 {%0,%1,%2,%3}, [%4];"
                 : "=f"(v.x), "=f"(v.y), "=f"(v.z), "=f"(v.w)
                 : "l"(p));
    return v;
}

__global__ __launch_bounds__(128, 3) void nslayer_kernel(
    const float* __restrict__ x_g,
    const float* __restrict__ w_g,
    float* __restrict__ out_g)
{
    const int m = blockIdx.x * blockDim.x + threadIdx.x;
    if (m >= NMAT) return;

    const float4* xm4 = reinterpret_cast<const float4*>(x_g + (size_t)m * 64);

    float w[8];
#pragma unroll
    for (int i = 0; i < 8; ++i) w[i] = __ldg(w_g + i);

    // ---- load x, build B = I - x^T x (upper triangle); x dies after this ----
    float B[36];
    {
        float x[64];
#pragma unroll
        for (int i = 0; i < 16; ++i) {
            float4 v = __ldg(xm4 + i);
            x[i * 4 + 0] = v.x;
            x[i * 4 + 1] = v.y;
            x[i * 4 + 2] = v.z;
            x[i * 4 + 3] = v.w;
        }
#pragma unroll
        for (int i = 0; i < 8; ++i) {
#pragma unroll
            for (int j = i; j < 8; ++j) {
                float s = x[0 * 8 + i] * x[0 * 8 + j];
#pragma unroll
                for (int k = 1; k < 8; ++k)
                    s = fmaf(x[k * 8 + i], x[k * 8 + j], s);
                B[tri(i, j)] = (i == j ? 1.0f : 0.0f) - s;
            }
        }
    }

    // ---- Horner chain on symmetric triangles ----
    float M0[36], M1[36];
#pragma unroll
    for (int i = 0; i < 8; ++i) {
#pragma unroll
        for (int j = i; j < 8; ++j)
            M0[tri(i, j)] = w[6] * B[tri(i, j)] + (i == j ? w[5] : 0.0f);
    }
    step(M1, B, M0, w[4]);
    step(M0, B, M1, w[3]);
    step(M1, B, M0, w[2]);
    step(M0, B, M1, w[1]);
    step(M1, B, M0, w[0]);
    step(M0, B, M1, 1.0f + w[7]);   // M0 = P = (1+w7) I + B*H

    // ---- out = x * P, streaming x row-by-row (reloaded, L1/L2-resident) ----
    float4* om4 = reinterpret_cast<float4*>(out_g + (size_t)m * 64);
#pragma unroll
    for (int i = 0; i < 8; ++i) {
        float4 a = ldg4v(xm4 + 2 * i);
        float4 b = ldg4v(xm4 + 2 * i + 1);
        float xr[8] = {a.x, a.y, a.z, a.w, b.x, b.y, b.z, b.w};

        float acc[8];
#pragma unroll
        for (int j = 0; j < 8; ++j) {
            float s = xr[0] * sg(M0, 0, j);
#pragma unroll
            for (int k = 1; k < 8; ++k)
                s = fmaf(xr[k], sg(M0, k, j), s);
            acc[j] = s;
        }
        float4 o0 = {acc[0], acc[1], acc[2], acc[3]};
        float4 o1 = {acc[4], acc[5], acc[6], acc[7]};
        om4[2 * i + 0] = o0;
        om4[2 * i + 1] = o1;
    }
}

extern "C" void kernel_launch(void* const* d_in, const int* in_sizes, int n_in,
                              void* d_out, int out_size) {
    const float* x_g = (const float*)d_in[0];   // (2048,128,8,8) fp32
    const float* w_g = (const float*)d_in[1];   // 14 fp32 (w[0..7] used)
    float* out_g = (float*)d_out;

    const int threads = 128;
    const int blocks = (NMAT + threads - 1) / threads;
    nslayer_kernel<<<blocks, threads>>>(x_g, w_g, out_g);
}

// round 6
// speedup vs baseline: 2.0715x; 1.0464x over previous
#include <cuda_runtime.h>

// NSLayer: out = x + (w0*A + ... + w6*A^7 + w7*I) @ x,  A = I - x x^T
// Gram-space: A^k x = x B^k, B = I - x^T x (symmetric).
//   out = x * P,  P = (1+w7) I + sum w_{k-1} B^k     (triangle Horner)
//
// R6: pack TWO matrices per thread lane-wise into f32x2 (fma.rn.f32x2) ->
// every fma covers both matrices; plus smem-staged coalesced I/O with an
// interleaved (a,b)-pair layout so LDS.64 yields ready-packed operands.

typedef unsigned long long ull;

#define NMAT (2048 * 128)
#define THREADS 128
#define MATS_PER_CTA 256                 // 2 per thread
#define PAIR_STRIDE 65                   // float2 units; odd -> conflict-free LDS.64
#define SMEM_BYTES (THREADS * PAIR_STRIDE * 8)

__device__ __forceinline__ int tri(int i, int j) {  // i <= j
    return i * 8 - (i * (i + 1)) / 2 + j;
}
__device__ __forceinline__ ull sg2(const ull* T, int i, int j) {
    return (i <= j) ? T[tri(i, j)] : T[tri(j, i)];
}

__device__ __forceinline__ ull pack2(float lo, float hi) {
    ull r; asm("mov.b64 %0,{%1,%2};" : "=l"(r) : "f"(lo), "f"(hi)); return r;
}
__device__ __forceinline__ ull fma2(ull a, ull b, ull c) {
    ull d; asm("fma.rn.f32x2 %0,%1,%2,%3;" : "=l"(d) : "l"(a), "l"(b), "l"(c)); return d;
}
__device__ __forceinline__ ull mul2(ull a, ull b) {
    ull d; asm("mul.rn.f32x2 %0,%1,%2;" : "=l"(d) : "l"(a), "l"(b)); return d;
}
__device__ __forceinline__ ull add2(ull a, ull b) {
    ull d; asm("add.rn.f32x2 %0,%1,%2;" : "=l"(d) : "l"(a), "l"(b)); return d;
}
// volatile scalar weight load: keeps each weight's live range to one step
__device__ __forceinline__ float ldw(const float* p) {
    float v; asm volatile("ld.global.nc.f32 %0,[%1];" : "=f"(v) : "l"(p)); return v;
}

// dst = B * src + wt * I   (symmetric triangles, packed pairs)
__device__ __forceinline__ void step2(ull* __restrict__ dst,
                                      const ull* __restrict__ B,
                                      const ull* __restrict__ src, ull wt2) {
#pragma unroll
    for (int i = 0; i < 8; ++i) {
#pragma unroll
        for (int j = i; j < 8; ++j) {
            ull s = mul2(sg2(B, i, 0), sg2(src, 0, j));
#pragma unroll
            for (int k = 1; k < 8; ++k)
                s = fma2(sg2(B, i, k), sg2(src, k, j), s);
            dst[tri(i, j)] = (i == j) ? add2(s, wt2) : s;
        }
    }
}

__global__ __launch_bounds__(THREADS, 2) void nslayer_kernel(
    const float* __restrict__ x_g,
    const float* __restrict__ w_g,
    float* __restrict__ out_g)
{
    extern __shared__ float sf[];
    const int tid = threadIdx.x;

    // ---- stage x: coalesced global -> interleaved-pair smem ----
    // block region: 256 matrices * 64 floats; pair p holds matrices (2p, 2p+1)
    // smem float offset of (matrix m, elem e): (m>>1)*130 + 2*e + (m&1)
    const float4* gx = reinterpret_cast<const float4*>(x_g)
                     + (size_t)blockIdx.x * (MATS_PER_CTA * 16);
#pragma unroll
    for (int it = 0; it < 32; ++it) {
        int idx = it * THREADS + tid;
        float4 v = gx[idx];
        int gf = idx << 2;
        int m = gf >> 6, e = gf & 63;
        float* s = sf + (m >> 1) * (2 * PAIR_STRIDE) + 2 * e + (m & 1);
        s[0] = v.x; s[2] = v.y; s[4] = v.z; s[6] = v.w;
    }
    __syncthreads();

    ull* my = reinterpret_cast<ull*>(sf) + tid * PAIR_STRIDE;

    // ---- Gram: B = I - x^T x  (packed triangle, built in place) ----
    ull B2[36];
    {
#pragma unroll
        for (int k = 0; k < 8; ++k) {
            ull xr[8];
#pragma unroll
            for (int c = 0; c < 8; ++c) xr[c] = my[k * 8 + c];
#pragma unroll
            for (int i = 0; i < 8; ++i)
#pragma unroll
                for (int j = i; j < 8; ++j) {
                    if (k == 0) B2[tri(i, j)] = mul2(xr[i], xr[j]);
                    else        B2[tri(i, j)] = fma2(xr[i], xr[j], B2[tri(i, j)]);
                }
        }
        const ull m1 = pack2(-1.0f, -1.0f);
        const ull one2 = pack2(1.0f, 1.0f);
#pragma unroll
        for (int i = 0; i < 8; ++i)
#pragma unroll
            for (int j = i; j < 8; ++j)
                B2[tri(i, j)] = fma2(B2[tri(i, j)], m1, (i == j) ? one2 : 0ull);
    }

    // ---- Horner on packed triangles ----
    ull M0[36], M1[36];
    {
        float w6 = ldw(w_g + 6), w5 = ldw(w_g + 5);
        ull w6_2 = pack2(w6, w6), w5_2 = pack2(w5, w5);
#pragma unroll
        for (int i = 0; i < 8; ++i)
#pragma unroll
            for (int j = i; j < 8; ++j) {
                ull v = mul2(B2[tri(i, j)], w6_2);
                M0[tri(i, j)] = (i == j) ? add2(v, w5_2) : v;
            }
    }
    { float w = ldw(w_g + 4); step2(M1, B2, M0, pack2(w, w)); }
    { float w = ldw(w_g + 3); step2(M0, B2, M1, pack2(w, w)); }
    { float w = ldw(w_g + 2); step2(M1, B2, M0, pack2(w, w)); }
    { float w = ldw(w_g + 1); step2(M0, B2, M1, pack2(w, w)); }
    { float w = ldw(w_g + 0); step2(M1, B2, M0, pack2(w, w)); }
    { float w = 1.0f + ldw(w_g + 7); step2(M0, B2, M1, pack2(w, w)); }
    // M0 = P (symmetric, packed)

    // ---- out = x * P, row by row, overwrite own smem region in place ----
#pragma unroll
    for (int i = 0; i < 8; ++i) {
        ull xr[8];
#pragma unroll
        for (int c = 0; c < 8; ++c) xr[c] = my[i * 8 + c];
#pragma unroll
        for (int j = 0; j < 8; ++j) {
            ull s = mul2(xr[0], sg2(M0, 0, j));
#pragma unroll
            for (int k = 1; k < 8; ++k)
                s = fma2(xr[k], sg2(M0, k, j), s);
            my[i * 8 + j] = s;
        }
    }
    __syncthreads();

    // ---- coalesced smem -> global store ----
    float4* go = reinterpret_cast<float4*>(out_g)
               + (size_t)blockIdx.x * (MATS_PER_CTA * 16);
#pragma unroll
    for (int it = 0; it < 32; ++it) {
        int idx = it * THREADS + tid;
        int gf = idx << 2;
        int m = gf >> 6, e = gf & 63;
        const float* s = sf + (m >> 1) * (2 * PAIR_STRIDE) + 2 * e + (m & 1);
        float4 v;
        v.x = s[0]; v.y = s[2]; v.z = s[4]; v.w = s[6];
        go[idx] = v;
    }
}

extern "C" void kernel_launch(void* const* d_in, const int* in_sizes, int n_in,
                              void* d_out, int out_size) {
    const float* x_g = (const float*)d_in[0];   // (2048,128,8,8) fp32
    const float* w_g = (const float*)d_in[1];   // 14 fp32 (w[0..7] used)
    float* out_g = (float*)d_out;

    cudaFuncSetAttribute(nslayer_kernel,
                         cudaFuncAttributeMaxDynamicSharedMemorySize, SMEM_BYTES);

    const int blocks = NMAT / MATS_PER_CTA;     // 1024
    nslayer_kernel<<<blocks, THREADS, SMEM_BYTES>>>(x_g, w_g, out_g);
}